// round 11
// baseline (speedup 1.0000x reference)
#include <cuda_runtime.h>
#include <cuda_bf16.h>
#include <cstdint>
#include <math.h>

#define HIDDEN 768
#define S_LEN  2048
#define B_SZ   4
#define NH     12
#define HD     64
#define M_TOTAL (B_SZ * S_LEN)   // 8192
#define GK 768
#define LOG2E 1.4426950408889634f
#define SCALEQ (0.125f * LOG2E)

typedef __nv_bfloat16 bf16;

// Pre-split scratch (device globals: allocation-free per harness rules)
__device__ bf16 g_Xh[M_TOTAL * GK], g_Xl[M_TOTAL * GK];
__device__ bf16 g_Wh[4][GK * GK],  g_Wl[4][GK * GK];   // q,k,v contiguous; o at [3]
__device__ bf16 g_Qh[M_TOTAL * GK], g_Ql[M_TOTAL * GK];
__device__ bf16 g_Kh[M_TOTAL * GK], g_Kl[M_TOTAL * GK];
__device__ bf16 g_Vh[M_TOTAL * GK], g_Vl[M_TOTAL * GK];
__device__ bf16 g_Ch[M_TOTAL * GK], g_Cl[M_TOTAL * GK];
__device__ float g_bias3[3 * GK];
__device__ float g_biasS[B_SZ * S_LEN];   // (1-mask)*(-10000*log2e)

// ===========================================================================
// Helpers
// ===========================================================================
__device__ __forceinline__ uint32_t smem_u32(const void* p) {
    uint32_t a;
    asm("{ .reg .u64 t; cvta.to.shared.u64 t, %1; cvt.u32.u64 %0, t; }"
        : "=r"(a) : "l"(p));
    return a;
}

__device__ __forceinline__ void ldsm_x4(uint32_t addr, uint32_t* r) {
    asm volatile("ldmatrix.sync.aligned.m8n8.x4.shared.b16 {%0,%1,%2,%3}, [%4];"
        : "=r"(r[0]), "=r"(r[1]), "=r"(r[2]), "=r"(r[3]) : "r"(addr));
}

__device__ __forceinline__ void ldsm_x4_t(uint32_t addr, uint32_t* r) {
    asm volatile("ldmatrix.sync.aligned.m8n8.x4.trans.shared.b16 {%0,%1,%2,%3}, [%4];"
        : "=r"(r[0]), "=r"(r[1]), "=r"(r[2]), "=r"(r[3]) : "r"(addr));
}

__device__ __forceinline__ void mma_bf16(float* d, const uint32_t* a,
                                         uint32_t b0, uint32_t b1) {
    asm volatile(
        "mma.sync.aligned.m16n8k16.row.col.f32.bf16.bf16.f32 "
        "{%0,%1,%2,%3}, {%4,%5,%6,%7}, {%8,%9}, {%0,%1,%2,%3};"
        : "+f"(d[0]), "+f"(d[1]), "+f"(d[2]), "+f"(d[3])
        : "r"(a[0]), "r"(a[1]), "r"(a[2]), "r"(a[3]), "r"(b0), "r"(b1));
}

__device__ __forceinline__ void split4(float4 v, uint2& hi, uint2& lo) {
    __nv_bfloat162 h0 = __floats2bfloat162_rn(v.x, v.y);
    __nv_bfloat162 h1 = __floats2bfloat162_rn(v.z, v.w);
    __nv_bfloat162 l0 = __floats2bfloat162_rn(v.x - __bfloat162float(h0.x),
                                              v.y - __bfloat162float(h0.y));
    __nv_bfloat162 l1 = __floats2bfloat162_rn(v.z - __bfloat162float(h1.x),
                                              v.w - __bfloat162float(h1.y));
    hi.x = *(uint32_t*)&h0; hi.y = *(uint32_t*)&h1;
    lo.x = *(uint32_t*)&l0; lo.y = *(uint32_t*)&l1;
}

__device__ __forceinline__ uint32_t pack_split(float x, float y, uint32_t& lo) {
    __nv_bfloat162 h = __floats2bfloat162_rn(x, y);
    __nv_bfloat162 l = __floats2bfloat162_rn(x - __bfloat162float(h.x),
                                             y - __bfloat162float(h.y));
    lo = *(uint32_t*)&l;
    return *(uint32_t*)&h;
}

__device__ __forceinline__ float ex2(float x) {
    float y;
    asm("ex2.approx.f32 %0, %1;" : "=f"(y) : "f"(x));
    return y;
}

__device__ __forceinline__ void cp16(uint32_t dst, const void* src) {
    asm volatile("cp.async.cg.shared.global [%0], [%1], 16;"
                 :: "r"(dst), "l"(src));
}
#define CP_COMMIT() asm volatile("cp.async.commit_group;" ::: "memory")
#define CP_WAIT0()  asm volatile("cp.async.wait_group 0;" ::: "memory")
#define CP_WAIT2()  asm volatile("cp.async.wait_group 2;" ::: "memory")

// ===========================================================================
// Prep kernels
// ===========================================================================
__global__ void split_kernel(const float* __restrict__ src,
                             bf16* __restrict__ dh, bf16* __restrict__ dl,
                             int n4)
{
    int i = blockIdx.x * blockDim.x + threadIdx.x;
    if (i < n4) {
        float4 v = *(const float4*)(src + (size_t)i * 4);
        uint2 h, l;
        split4(v, h, l);
        *(uint2*)(dh + (size_t)i * 4) = h;
        *(uint2*)(dl + (size_t)i * 4) = l;
    }
}

__global__ void split4w_kernel(const float* __restrict__ w0,
                               const float* __restrict__ w1,
                               const float* __restrict__ w2,
                               const float* __restrict__ w3,
                               bf16* __restrict__ dh, bf16* __restrict__ dl)
{
    const int per = GK * GK / 4;
    int i = blockIdx.x * blockDim.x + threadIdx.x;
    if (i >= 4 * per) return;
    int sec = i / per, off = i - sec * per;
    const float* src = (sec == 0) ? w0 : (sec == 1) ? w1 : (sec == 2) ? w2 : w3;
    float4 v = *(const float4*)(src + (size_t)off * 4);
    uint2 h, l;
    split4(v, h, l);
    *(uint2*)(dh + (size_t)sec * GK * GK + (size_t)off * 4) = h;
    *(uint2*)(dl + (size_t)sec * GK * GK + (size_t)off * 4) = l;
}

// bias concat + mask bias in one launch (covers max(3*GK, B*S) = 8192)
__global__ void prep_misc_kernel(const float* __restrict__ bq,
                                 const float* __restrict__ bk,
                                 const float* __restrict__ bv,
                                 const float* __restrict__ mask,
                                 float* __restrict__ b3,
                                 float* __restrict__ biasS)
{
    int i = blockIdx.x * blockDim.x + threadIdx.x;
    if (i < GK) b3[i] = bq[i];
    else if (i < 2 * GK) b3[i] = bk[i - GK];
    else if (i < 3 * GK) b3[i] = bv[i - 2 * GK];
    if (i < B_SZ * S_LEN)
        biasS[i] = (1.0f - mask[i]) * (-10000.0f * LOG2E);
}

// ===========================================================================
// GEMM: out = alpha*(A @ W^T + bias). Pre-split bf16 hi/lo operands.
// CTA 128x128, 8 warps (64x32 each). 4-stage cp.async pipeline, BK=16:
// prefetch distance 3 iters (~300 cyc) covers L2 latency (234-262 cyc).
// Same per-16k accumulation order as before -> bitwise-identical results.
// ===========================================================================
#define GSTR 48                      // bytes per smem row (16 bf16 + 16B pad)
#define GTILE (128 * GSTR)           // 6144
#define GSTAGE (4 * GTILE)           // 24576
#define GSTAGES 4
#define GEMM_SMEM_BYTES (GSTAGES * GSTAGE)   // 98304
#define KSTEPS48 48                  // 768 / 16

__global__ __launch_bounds__(256, 2)
void gemm_bf16_kernel(const bf16* __restrict__ Ah, const bf16* __restrict__ Al,
                      const bf16* __restrict__ Wh, const bf16* __restrict__ Wl,
                      const float* __restrict__ bias,
                      bf16* __restrict__ O0h, bf16* __restrict__ O0l,
                      bf16* __restrict__ O1h, bf16* __restrict__ O1l,
                      bf16* __restrict__ O2h, bf16* __restrict__ O2l,
                      float* __restrict__ Cf)
{
    extern __shared__ char smc[];
    const uint32_t sb = smem_u32(smc);
    const int tid  = threadIdx.x;
    const int lane = tid & 31;
    const int wid  = tid >> 5;
    const int bm = blockIdx.y * 128;
    const int bn = blockIdx.x * 128;
    const int wm = (wid & 1) * 64;
    const int wn = (wid >> 1) * 32;

    const int sec  = bn / GK;
    const int colb = bn - sec * GK;
    const float alpha = (Cf == nullptr && sec == 0) ? SCALEQ : 1.0f;
    bf16* Ho = (sec == 0) ? O0h : (sec == 1) ? O1h : O2h;
    bf16* Lo = (sec == 0) ? O0l : (sec == 1) ? O1l : O2l;

    const bf16* srcs[4] = { Ah + (size_t)bm * GK, Al + (size_t)bm * GK,
                            Wh + (size_t)bn * GK, Wl + (size_t)bn * GK };

    // loader mapping: 256 threads cover 128 rows x 2 16B-chunks per part
    const int l_row = tid >> 1;
    const int l_kc  = tid & 1;

    auto issue = [&](int s, int buf) {
        const uint32_t dbase = sb + (uint32_t)(buf * GSTAGE)
                             + (uint32_t)(l_row * GSTR + l_kc * 16);
        const size_t goff = (size_t)l_row * GK + s * 16 + l_kc * 8;
        #pragma unroll
        for (int p = 0; p < 4; p++)
            cp16(dbase + (uint32_t)(p * GTILE), srcs[p] + goff);
    };

    // prologue: 3 stages in flight
    issue(0, 0); CP_COMMIT();
    issue(1, 1); CP_COMMIT();
    issue(2, 2); CP_COMMIT();

    float acc[4][4][4] = {};
    const int frag_r = lane & 15;
    const int kbyte  = ((lane >> 4) << 3) * 2;   // 0 or 16

    for (int s = 0; s < KSTEPS48; s++) {
        CP_WAIT2();               // stage s complete (3+s commits, keep <=2)
        __syncthreads();
        if (s + 3 < KSTEPS48) issue(s + 3, (s + 3) & 3);
        CP_COMMIT();              // always commit (possibly empty) group
        const uint32_t stg = sb + (uint32_t)((s & 3) * GSTAGE);

        uint32_t ah[4][4], al[4][4], wh[2][4], wl[2][4];
        #pragma unroll
        for (int mi = 0; mi < 4; mi++) {
            uint32_t ro = (uint32_t)((wm + mi * 16 + frag_r) * GSTR) + kbyte;
            ldsm_x4(stg + 0 * GTILE + ro, ah[mi]);
            ldsm_x4(stg + 1 * GTILE + ro, al[mi]);
        }
        #pragma unroll
        for (int np = 0; np < 2; np++) {
            uint32_t ro = (uint32_t)((wn + np * 16 + frag_r) * GSTR) + kbyte;
            ldsm_x4(stg + 2 * GTILE + ro, wh[np]);
            ldsm_x4(stg + 3 * GTILE + ro, wl[np]);
        }
        #pragma unroll
        for (int mi = 0; mi < 4; mi++)
            #pragma unroll
            for (int nj = 0; nj < 4; nj++) {
                const int np = nj >> 1, sub = nj & 1;
                mma_bf16(acc[mi][nj], ah[mi], wh[np][sub], wh[np][sub + 2]);
            }
        #pragma unroll
        for (int mi = 0; mi < 4; mi++)
            #pragma unroll
            for (int nj = 0; nj < 4; nj++) {
                const int np = nj >> 1, sub = nj & 1;
                mma_bf16(acc[mi][nj], ah[mi], wl[np][sub], wl[np][sub + 2]);
            }
        #pragma unroll
        for (int mi = 0; mi < 4; mi++)
            #pragma unroll
            for (int nj = 0; nj < 4; nj++) {
                const int np = nj >> 1, sub = nj & 1;
                mma_bf16(acc[mi][nj], al[mi], wh[np][sub], wh[np][sub + 2]);
            }
        // no trailing sync: next iteration's wait+sync separates compute(s)
        // from the buffer-reusing issue(s+4).
    }

    const int gr = lane >> 2;
    const int cp = (lane & 3) * 2;
    #pragma unroll
    for (int mi = 0; mi < 4; mi++) {
        #pragma unroll
        for (int nj = 0; nj < 4; nj++) {
            int row0 = bm + wm + mi * 16 + gr;
            int colg = colb + wn + nj * 8 + cp;
            int bcol = bn + wn + nj * 8 + cp;
            float b0 = bias[bcol], b1 = bias[bcol + 1];
            float v00 = alpha * (acc[mi][nj][0] + b0);
            float v01 = alpha * (acc[mi][nj][1] + b1);
            float v10 = alpha * (acc[mi][nj][2] + b0);
            float v11 = alpha * (acc[mi][nj][3] + b1);
            if (Cf) {
                float2 f0 = { v00, v01 }, f1 = { v10, v11 };
                *(float2*)&Cf[(size_t)row0 * GK + colg] = f0;
                *(float2*)&Cf[(size_t)(row0 + 8) * GK + colg] = f1;
            } else {
                uint32_t l0, l1;
                uint32_t h0 = pack_split(v00, v01, l0);
                uint32_t h1 = pack_split(v10, v11, l1);
                *(uint32_t*)&Ho[(size_t)row0 * GK + colg] = h0;
                *(uint32_t*)&Lo[(size_t)row0 * GK + colg] = l0;
                *(uint32_t*)&Ho[(size_t)(row0 + 8) * GK + colg] = h1;
                *(uint32_t*)&Lo[(size_t)(row0 + 8) * GK + colg] = l1;
            }
        }
    }
}

// ===========================================================================
// Flash attention (R10 proven version, unchanged).
// 4 warps x 32 q-rows (mi=2), k-tile 64, term-major MMA order.
// ===========================================================================
#define ASTR 144
#define AQH_O 0
#define AQL_O (128 * ASTR)
#define ASTG0 (2 * 128 * ASTR)
#define AKH_O 0
#define AKL_O (64 * ASTR)
#define AVH_O (2 * 64 * ASTR)
#define AVL_O (3 * 64 * ASTR)
#define ABI_O (4 * 64 * ASTR)
#define ASTG_SZ (ABI_O + 256)
#define ATTN_SMEM_BYTES (ASTG0 + 2 * ASTG_SZ)   // 111104

__global__ __launch_bounds__(128, 2)
void attn_bf16_kernel(const bf16* __restrict__ Qh, const bf16* __restrict__ Ql,
                      const bf16* __restrict__ Kh, const bf16* __restrict__ Kl,
                      const bf16* __restrict__ Vh, const bf16* __restrict__ Vl,
                      const float* __restrict__ biasS,
                      bf16* __restrict__ Ch, bf16* __restrict__ Cl)
{
    extern __shared__ char smc[];
    const uint32_t sb = smem_u32(smc);
    const int b  = blockIdx.z;
    const int h  = blockIdx.y;
    const int qt = blockIdx.x;
    const int tid  = threadIdx.x;
    const int lane = tid & 31;
    const int wid  = tid >> 5;        // 0..3

    const int t  = lane & 3;
    const int gr = lane >> 2;
    const int frag_r = lane & 15;
    const int frag_k = (lane >> 4) << 3;
    const int v_kr = (lane & 7) + ((lane >> 4) << 3);
    const int v_nc = (lane & 8);

    const size_t qbase = ((size_t)b * S_LEN + (size_t)qt * 128) * GK + h * HD;

    auto issue_stage = [&](int kt, int buf) {
        const uint32_t dbase = sb + (uint32_t)(ASTG0 + buf * ASTG_SZ);
        const size_t off = ((size_t)b * S_LEN + (size_t)kt * 64) * GK + h * HD;
        const bf16* bases[4] = { Kh + off, Kl + off, Vh + off, Vl + off };
        #pragma unroll
        for (int p = 0; p < 4; p++) {
            #pragma unroll
            for (int i = 0; i < 4; i++) {
                int idx = tid + i * 128;
                int row = idx >> 3, kc = idx & 7;
                cp16(dbase + (uint32_t)(p * (64 * ASTR) + row * ASTR + kc * 16),
                     bases[p] + (size_t)row * GK + kc * 8);
            }
        }
        if (tid < 16)
            cp16(dbase + (uint32_t)(ABI_O + tid * 16),
                 biasS + (size_t)b * S_LEN + kt * 64 + tid * 4);
    };

    {
        #pragma unroll
        for (int i = 0; i < 8; i++) {
            int idx = tid + i * 128;
            int row = idx >> 3, kc = idx & 7;
            cp16(sb + (uint32_t)(AQH_O + row * ASTR + kc * 16),
                 Qh + qbase + (size_t)row * GK + kc * 8);
            cp16(sb + (uint32_t)(AQL_O + row * ASTR + kc * 16),
                 Ql + qbase + (size_t)row * GK + kc * 8);
        }
        issue_stage(0, 0);
        CP_COMMIT();
    }

    float o[2][8][4] = {};
    float m[2][2] = { { -1e30f, -1e30f }, { -1e30f, -1e30f } };
    float l[2][2] = {};

    for (int kt = 0; kt < S_LEN / 64; kt++) {
        CP_WAIT0();
        __syncthreads();
        if (kt + 1 < S_LEN / 64) {
            issue_stage(kt + 1, (kt + 1) & 1);
            CP_COMMIT();
        }
        const uint32_t stg = sb + (uint32_t)(ASTG0 + (kt & 1) * ASTG_SZ);
        const float* Bs = (const float*)(smc + ASTG0 + (kt & 1) * ASTG_SZ + ABI_O);

        // ---- S = Q K^T (3-term split, term-major per np)
        float s[2][8][4] = {};
        #pragma unroll
        for (int kk = 0; kk < 4; kk++) {
            const uint32_t kbyte = (uint32_t)((kk * 16 + frag_k) * 2);
            uint32_t ah[2][4], al[2][4];
            #pragma unroll
            for (int mi = 0; mi < 2; mi++) {
                uint32_t qo = (uint32_t)((wid * 32 + mi * 16 + frag_r) * ASTR) + kbyte;
                ldsm_x4(sb + AQH_O + qo, ah[mi]);
                ldsm_x4(sb + AQL_O + qo, al[mi]);
            }
            #pragma unroll
            for (int np = 0; np < 4; np++) {
                uint32_t kh[4], kl[4];
                uint32_t ko = (uint32_t)((np * 16 + frag_r) * ASTR) + kbyte;
                ldsm_x4(stg + AKH_O + ko, kh);
                ldsm_x4(stg + AKL_O + ko, kl);
                #pragma unroll
                for (int sub = 0; sub < 2; sub++)
                    #pragma unroll
                    for (int mi = 0; mi < 2; mi++)
                        mma_bf16(s[mi][np * 2 + sub], ah[mi], kh[sub], kh[sub + 2]);
                #pragma unroll
                for (int sub = 0; sub < 2; sub++)
                    #pragma unroll
                    for (int mi = 0; mi < 2; mi++)
                        mma_bf16(s[mi][np * 2 + sub], ah[mi], kl[sub], kl[sub + 2]);
                #pragma unroll
                for (int sub = 0; sub < 2; sub++)
                    #pragma unroll
                    for (int mi = 0; mi < 2; mi++)
                        mma_bf16(s[mi][np * 2 + sub], al[mi], kh[sub], kh[sub + 2]);
            }
        }

        // ---- online softmax (exp2 domain, precomputed bias)
        float bb0[8], bb1[8];
        #pragma unroll
        for (int nj = 0; nj < 8; nj++) {
            bb0[nj] = Bs[nj * 8 + 2 * t];
            bb1[nj] = Bs[nj * 8 + 2 * t + 1];
        }
        #pragma unroll
        for (int mi = 0; mi < 2; mi++) {
            float m0n = -1e30f, m1n = -1e30f;
            #pragma unroll
            for (int nj = 0; nj < 8; nj++) {
                s[mi][nj][0] += bb0[nj]; s[mi][nj][1] += bb1[nj];
                s[mi][nj][2] += bb0[nj]; s[mi][nj][3] += bb1[nj];
                m0n = fmaxf(m0n, fmaxf(s[mi][nj][0], s[mi][nj][1]));
                m1n = fmaxf(m1n, fmaxf(s[mi][nj][2], s[mi][nj][3]));
            }
            m0n = fmaxf(m0n, __shfl_xor_sync(0xffffffffu, m0n, 1));
            m0n = fmaxf(m0n, __shfl_xor_sync(0xffffffffu, m0n, 2));
            m1n = fmaxf(m1n, __shfl_xor_sync(0xffffffffu, m1n, 1));
            m1n = fmaxf(m1n, __shfl_xor_sync(0xffffffffu, m1n, 2));
            float m0w = fmaxf(m[mi][0], m0n);
            float m1w = fmaxf(m[mi][1], m1n);
            float a0 = ex2(m[mi][0] - m0w);
            float a1 = ex2(m[mi][1] - m1w);
            float sum0 = 0.0f, sum1 = 0.0f;
            #pragma unroll
            for (int nj = 0; nj < 8; nj++) {
                s[mi][nj][0] = ex2(s[mi][nj][0] - m0w);
                s[mi][nj][1] = ex2(s[mi][nj][1] - m0w);
                s[mi][nj][2] = ex2(s[mi][nj][2] - m1w);
                s[mi][nj][3] = ex2(s[mi][nj][3] - m1w);
                sum0 += s[mi][nj][0] + s[mi][nj][1];
                sum1 += s[mi][nj][2] + s[mi][nj][3];
            }
            l[mi][0] = l[mi][0] * a0 + sum0;
            l[mi][1] = l[mi][1] * a1 + sum1;
            m[mi][0] = m0w; m[mi][1] = m1w;
            #pragma unroll
            for (int nd = 0; nd < 8; nd++) {
                o[mi][nd][0] *= a0; o[mi][nd][1] *= a0;
                o[mi][nd][2] *= a1; o[mi][nd][3] *= a1;
            }
        }

        // ---- O += P V (3-term split, term-major per np; V via ldmatrix.trans)
        #pragma unroll
        for (int kk = 0; kk < 4; kk++) {
            const int j0 = 2 * kk, j1 = 2 * kk + 1;
            uint32_t pah[2][4], pal[2][4];
            #pragma unroll
            for (int mi = 0; mi < 2; mi++) {
                pah[mi][0] = pack_split(s[mi][j0][0], s[mi][j0][1], pal[mi][0]);
                pah[mi][1] = pack_split(s[mi][j0][2], s[mi][j0][3], pal[mi][1]);
                pah[mi][2] = pack_split(s[mi][j1][0], s[mi][j1][1], pal[mi][2]);
                pah[mi][3] = pack_split(s[mi][j1][2], s[mi][j1][3], pal[mi][3]);
            }
            #pragma unroll
            for (int np = 0; np < 4; np++) {
                uint32_t vh[4], vl[4];
                uint32_t vo = (uint32_t)((kk * 16 + v_kr) * ASTR
                                         + (np * 16 + v_nc) * 2);
                ldsm_x4_t(stg + AVH_O + vo, vh);
                ldsm_x4_t(stg + AVL_O + vo, vl);
                #pragma unroll
                for (int sub = 0; sub < 2; sub++)
                    #pragma unroll
                    for (int mi = 0; mi < 2; mi++)
                        mma_bf16(o[mi][np * 2 + sub], pah[mi], vh[sub], vh[sub + 2]);
                #pragma unroll
                for (int sub = 0; sub < 2; sub++)
                    #pragma unroll
                    for (int mi = 0; mi < 2; mi++)
                        mma_bf16(o[mi][np * 2 + sub], pah[mi], vl[sub], vl[sub + 2]);
                #pragma unroll
                for (int sub = 0; sub < 2; sub++)
                    #pragma unroll
                    for (int mi = 0; mi < 2; mi++)
                        mma_bf16(o[mi][np * 2 + sub], pal[mi], vh[sub], vh[sub + 2]);
            }
        }
        // no trailing sync (next iter's CP_WAIT0+__syncthreads suffices)
    }

    // final l reduce + write out (pre-split bf16)
    #pragma unroll
    for (int mi = 0; mi < 2; mi++) {
        float l0 = l[mi][0], l1 = l[mi][1];
        l0 += __shfl_xor_sync(0xffffffffu, l0, 1);
        l0 += __shfl_xor_sync(0xffffffffu, l0, 2);
        l1 += __shfl_xor_sync(0xffffffffu, l1, 1);
        l1 += __shfl_xor_sync(0xffffffffu, l1, 2);
        float inv0 = 1.0f / l0;
        float inv1 = 1.0f / l1;

        const size_t row0 = (size_t)b * S_LEN + (size_t)qt * 128
                          + wid * 32 + mi * 16 + gr;
        const size_t cb = row0 * GK + h * HD;
        #pragma unroll
        for (int nd = 0; nd < 8; nd++) {
            int col = nd * 8 + 2 * t;
            uint32_t lo0, lo1;
            uint32_t h0 = pack_split(o[mi][nd][0] * inv0, o[mi][nd][1] * inv0, lo0);
            uint32_t h1 = pack_split(o[mi][nd][2] * inv1, o[mi][nd][3] * inv1, lo1);
            *(uint32_t*)&Ch[cb + col] = h0;
            *(uint32_t*)&Cl[cb + col] = lo0;
            *(uint32_t*)&Ch[cb + (size_t)8 * GK + col] = h1;
            *(uint32_t*)&Cl[cb + (size_t)8 * GK + col] = lo1;
        }
    }
}

// ---------------------------------------------------------------------------
extern "C" void kernel_launch(void* const* d_in, const int* in_sizes, int n_in,
                              void* d_out, int out_size)
{
    const float* X    = (const float*)d_in[0];
    const float* mask = (const float*)d_in[1];
    const float* Wq   = (const float*)d_in[2];
    const float* bq   = (const float*)d_in[3];
    const float* Wk   = (const float*)d_in[4];
    const float* bk   = (const float*)d_in[5];
    const float* Wv   = (const float*)d_in[6];
    const float* bv   = (const float*)d_in[7];
    const float* Wo   = (const float*)d_in[8];
    const float* bo   = (const float*)d_in[9];
    float* out = (float*)d_out;

    bf16 *xh, *xl, *wh, *wl, *qh, *ql, *kh, *kl, *vh, *vl, *ch, *cl;
    float *b3, *bs;
    cudaGetSymbolAddress((void**)&xh, g_Xh);
    cudaGetSymbolAddress((void**)&xl, g_Xl);
    cudaGetSymbolAddress((void**)&wh, g_Wh);
    cudaGetSymbolAddress((void**)&wl, g_Wl);
    cudaGetSymbolAddress((void**)&qh, g_Qh);
    cudaGetSymbolAddress((void**)&ql, g_Ql);
    cudaGetSymbolAddress((void**)&kh, g_Kh);
    cudaGetSymbolAddress((void**)&kl, g_Kl);
    cudaGetSymbolAddress((void**)&vh, g_Vh);
    cudaGetSymbolAddress((void**)&vl, g_Vl);
    cudaGetSymbolAddress((void**)&ch, g_Ch);
    cudaGetSymbolAddress((void**)&cl, g_Cl);
    cudaGetSymbolAddress((void**)&b3, g_bias3);
    cudaGetSymbolAddress((void**)&bs, g_biasS);

    cudaFuncSetAttribute(gemm_bf16_kernel,
                         cudaFuncAttributeMaxDynamicSharedMemorySize,
                         GEMM_SMEM_BYTES);
    cudaFuncSetAttribute(attn_bf16_kernel,
                         cudaFuncAttributeMaxDynamicSharedMemorySize,
                         ATTN_SMEM_BYTES);

    // prep: X split, weights split (one launch), bias+mask prep (one launch)
    split_kernel<<<(M_TOTAL * GK / 4 + 255) / 256, 256>>>(X, xh, xl, M_TOTAL * GK / 4);
    split4w_kernel<<<(4 * GK * GK / 4 + 255) / 256, 256>>>(Wq, Wk, Wv, Wo, wh, wl);
    prep_misc_kernel<<<(B_SZ * S_LEN + 255) / 256, 256>>>(bq, bk, bv, mask, b3, bs);

    // fused QKV projection: N = 2304
    dim3 fgrid(3 * GK / 128, M_TOTAL / 128);   // (18, 64)
    gemm_bf16_kernel<<<fgrid, 256, GEMM_SMEM_BYTES>>>(
        xh, xl, wh, wl, b3, qh, ql, kh, kl, vh, vl, nullptr);

    dim3 agrid(S_LEN / 128, NH, B_SZ);         // (16, 12, 4)
    attn_bf16_kernel<<<agrid, 128, ATTN_SMEM_BYTES>>>(
        qh, ql, kh, kl, vh, vl, bs, ch, cl);

    // output projection (fp32 out)
    dim3 ogrid(GK / 128, M_TOTAL / 128);       // (6, 64)
    gemm_bf16_kernel<<<ogrid, 256, GEMM_SMEM_BYTES>>>(
        ch, cl, wh + 3 * GK * GK, wl + 3 * GK * GK, bo,
        nullptr, nullptr, nullptr, nullptr, nullptr, nullptr, out);
}

// round 12
// speedup vs baseline: 1.0476x; 1.0476x over previous
#include <cuda_runtime.h>
#include <cuda_bf16.h>
#include <cstdint>
#include <math.h>

#define HIDDEN 768
#define S_LEN  2048
#define B_SZ   4
#define NH     12
#define HD     64
#define M_TOTAL (B_SZ * S_LEN)   // 8192
#define GK 768
#define LOG2E 1.4426950408889634f
#define SCALEQ (0.125f * LOG2E)

typedef __nv_bfloat16 bf16;

// Pre-split scratch (device globals: allocation-free per harness rules)
__device__ bf16 g_Xh[M_TOTAL * GK], g_Xl[M_TOTAL * GK];
__device__ bf16 g_Wh[4][GK * GK],  g_Wl[4][GK * GK];   // q,k,v contiguous; o at [3]
__device__ bf16 g_Qh[M_TOTAL * GK], g_Ql[M_TOTAL * GK];
__device__ bf16 g_Kh[M_TOTAL * GK], g_Kl[M_TOTAL * GK];
__device__ bf16 g_Vh[M_TOTAL * GK], g_Vl[M_TOTAL * GK];
__device__ bf16 g_Ch[M_TOTAL * GK], g_Cl[M_TOTAL * GK];
__device__ float g_bias3[3 * GK];
__device__ float g_biasS[B_SZ * S_LEN];   // (1-mask)*(-10000*log2e)

// ===========================================================================
// Helpers
// ===========================================================================
__device__ __forceinline__ uint32_t smem_u32(const void* p) {
    uint32_t a;
    asm("{ .reg .u64 t; cvta.to.shared.u64 t, %1; cvt.u32.u64 %0, t; }"
        : "=r"(a) : "l"(p));
    return a;
}

__device__ __forceinline__ void ldsm_x4(uint32_t addr, uint32_t* r) {
    asm volatile("ldmatrix.sync.aligned.m8n8.x4.shared.b16 {%0,%1,%2,%3}, [%4];"
        : "=r"(r[0]), "=r"(r[1]), "=r"(r[2]), "=r"(r[3]) : "r"(addr));
}

__device__ __forceinline__ void ldsm_x4_t(uint32_t addr, uint32_t* r) {
    asm volatile("ldmatrix.sync.aligned.m8n8.x4.trans.shared.b16 {%0,%1,%2,%3}, [%4];"
        : "=r"(r[0]), "=r"(r[1]), "=r"(r[2]), "=r"(r[3]) : "r"(addr));
}

__device__ __forceinline__ void mma_bf16(float* d, const uint32_t* a,
                                         uint32_t b0, uint32_t b1) {
    asm volatile(
        "mma.sync.aligned.m16n8k16.row.col.f32.bf16.bf16.f32 "
        "{%0,%1,%2,%3}, {%4,%5,%6,%7}, {%8,%9}, {%0,%1,%2,%3};"
        : "+f"(d[0]), "+f"(d[1]), "+f"(d[2]), "+f"(d[3])
        : "r"(a[0]), "r"(a[1]), "r"(a[2]), "r"(a[3]), "r"(b0), "r"(b1));
}

__device__ __forceinline__ void split4(float4 v, uint2& hi, uint2& lo) {
    __nv_bfloat162 h0 = __floats2bfloat162_rn(v.x, v.y);
    __nv_bfloat162 h1 = __floats2bfloat162_rn(v.z, v.w);
    __nv_bfloat162 l0 = __floats2bfloat162_rn(v.x - __bfloat162float(h0.x),
                                              v.y - __bfloat162float(h0.y));
    __nv_bfloat162 l1 = __floats2bfloat162_rn(v.z - __bfloat162float(h1.x),
                                              v.w - __bfloat162float(h1.y));
    hi.x = *(uint32_t*)&h0; hi.y = *(uint32_t*)&h1;
    lo.x = *(uint32_t*)&l0; lo.y = *(uint32_t*)&l1;
}

__device__ __forceinline__ uint32_t pack_split(float x, float y, uint32_t& lo) {
    __nv_bfloat162 h = __floats2bfloat162_rn(x, y);
    __nv_bfloat162 l = __floats2bfloat162_rn(x - __bfloat162float(h.x),
                                             y - __bfloat162float(h.y));
    lo = *(uint32_t*)&l;
    return *(uint32_t*)&h;
}

__device__ __forceinline__ float ex2(float x) {
    float y;
    asm("ex2.approx.f32 %0, %1;" : "=f"(y) : "f"(x));
    return y;
}

__device__ __forceinline__ void cp16(uint32_t dst, const void* src) {
    asm volatile("cp.async.cg.shared.global [%0], [%1], 16;"
                 :: "r"(dst), "l"(src));
}
#define CP_COMMIT() asm volatile("cp.async.commit_group;" ::: "memory")
#define CP_WAIT0()  asm volatile("cp.async.wait_group 0;" ::: "memory")

// ===========================================================================
// Prep kernels
// ===========================================================================
__global__ void split_kernel(const float* __restrict__ src,
                             bf16* __restrict__ dh, bf16* __restrict__ dl,
                             int n4)
{
    int i = blockIdx.x * blockDim.x + threadIdx.x;
    if (i < n4) {
        float4 v = *(const float4*)(src + (size_t)i * 4);
        uint2 h, l;
        split4(v, h, l);
        *(uint2*)(dh + (size_t)i * 4) = h;
        *(uint2*)(dl + (size_t)i * 4) = l;
    }
}

__global__ void split4w_kernel(const float* __restrict__ w0,
                               const float* __restrict__ w1,
                               const float* __restrict__ w2,
                               const float* __restrict__ w3,
                               bf16* __restrict__ dh, bf16* __restrict__ dl)
{
    const int per = GK * GK / 4;
    int i = blockIdx.x * blockDim.x + threadIdx.x;
    if (i >= 4 * per) return;
    int sec = i / per, off = i - sec * per;
    const float* src = (sec == 0) ? w0 : (sec == 1) ? w1 : (sec == 2) ? w2 : w3;
    float4 v = *(const float4*)(src + (size_t)off * 4);
    uint2 h, l;
    split4(v, h, l);
    *(uint2*)(dh + (size_t)sec * GK * GK + (size_t)off * 4) = h;
    *(uint2*)(dl + (size_t)sec * GK * GK + (size_t)off * 4) = l;
}

// bias concat + mask bias in one launch (covers max(3*GK, B*S) = 8192)
__global__ void prep_misc_kernel(const float* __restrict__ bq,
                                 const float* __restrict__ bk,
                                 const float* __restrict__ bv,
                                 const float* __restrict__ mask,
                                 float* __restrict__ b3,
                                 float* __restrict__ biasS)
{
    int i = blockIdx.x * blockDim.x + threadIdx.x;
    if (i < GK) b3[i] = bq[i];
    else if (i < 2 * GK) b3[i] = bk[i - GK];
    else if (i < 3 * GK) b3[i] = bv[i - 2 * GK];
    if (i < B_SZ * S_LEN)
        biasS[i] = (1.0f - mask[i]) * (-10000.0f * LOG2E);
}

// ===========================================================================
// GEMM (R10 proven version: BK=32, 2-stage cp.async, term-major MMA order)
// ===========================================================================
#define GSTR 80
#define GTILE (128 * GSTR)
#define GSTAGE (4 * GTILE)
#define GEMM_SMEM_BYTES (2 * GSTAGE)

__global__ __launch_bounds__(256, 2)
void gemm_bf16_kernel(const bf16* __restrict__ Ah, const bf16* __restrict__ Al,
                      const bf16* __restrict__ Wh, const bf16* __restrict__ Wl,
                      const float* __restrict__ bias,
                      bf16* __restrict__ O0h, bf16* __restrict__ O0l,
                      bf16* __restrict__ O1h, bf16* __restrict__ O1l,
                      bf16* __restrict__ O2h, bf16* __restrict__ O2l,
                      float* __restrict__ Cf)
{
    extern __shared__ char smc[];
    const uint32_t sb = smem_u32(smc);
    const int tid  = threadIdx.x;
    const int lane = tid & 31;
    const int wid  = tid >> 5;
    const int bm = blockIdx.y * 128;
    const int bn = blockIdx.x * 128;
    const int wm = (wid & 1) * 64;
    const int wn = (wid >> 1) * 32;

    const int sec  = bn / GK;
    const int colb = bn - sec * GK;
    const float alpha = (Cf == nullptr && sec == 0) ? SCALEQ : 1.0f;
    bf16* Ho = (sec == 0) ? O0h : (sec == 1) ? O1h : O2h;
    bf16* Lo = (sec == 0) ? O0l : (sec == 1) ? O1l : O2l;

    const bf16* srcs[4] = { Ah + (size_t)bm * GK, Al + (size_t)bm * GK,
                            Wh + (size_t)bn * GK, Wl + (size_t)bn * GK };

    auto issue = [&](int s, int buf) {
        const uint32_t dbase = sb + (uint32_t)(buf * GSTAGE);
        #pragma unroll
        for (int p = 0; p < 4; p++) {
            const bf16* base = srcs[p] + s * 32;
            #pragma unroll
            for (int i = 0; i < 2; i++) {
                int idx = tid + i * 256;
                int row = idx >> 2, kc = idx & 3;
                cp16(dbase + (uint32_t)(p * GTILE + row * GSTR + kc * 16),
                     base + (size_t)row * GK + kc * 8);
            }
        }
    };

    issue(0, 0);
    CP_COMMIT();

    float acc[4][4][4] = {};
    const int frag_r = lane & 15;
    const int frag_k = (lane >> 4) << 3;

    #define KSTEPS24 24
    for (int s = 0; s < KSTEPS24; s++) {
        CP_WAIT0();
        __syncthreads();
        if (s + 1 < KSTEPS24) {
            issue(s + 1, (s + 1) & 1);
            CP_COMMIT();
        }
        const uint32_t stg = sb + (uint32_t)((s & 1) * GSTAGE);
        #pragma unroll
        for (int kk = 0; kk < 2; kk++) {
            const uint32_t kbyte = (uint32_t)((kk * 16 + frag_k) * 2);
            uint32_t ah[4][4], al[4][4], wh[2][4], wl[2][4];
            #pragma unroll
            for (int mi = 0; mi < 4; mi++) {
                uint32_t ro = (uint32_t)((wm + mi * 16 + frag_r) * GSTR) + kbyte;
                ldsm_x4(stg + 0 * GTILE + ro, ah[mi]);
                ldsm_x4(stg + 1 * GTILE + ro, al[mi]);
            }
            #pragma unroll
            for (int np = 0; np < 2; np++) {
                uint32_t ro = (uint32_t)((wn + np * 16 + frag_r) * GSTR) + kbyte;
                ldsm_x4(stg + 2 * GTILE + ro, wh[np]);
                ldsm_x4(stg + 3 * GTILE + ro, wl[np]);
            }
            #pragma unroll
            for (int mi = 0; mi < 4; mi++)
                #pragma unroll
                for (int nj = 0; nj < 4; nj++) {
                    const int np = nj >> 1, sub = nj & 1;
                    mma_bf16(acc[mi][nj], ah[mi], wh[np][sub], wh[np][sub + 2]);
                }
            #pragma unroll
            for (int mi = 0; mi < 4; mi++)
                #pragma unroll
                for (int nj = 0; nj < 4; nj++) {
                    const int np = nj >> 1, sub = nj & 1;
                    mma_bf16(acc[mi][nj], ah[mi], wl[np][sub], wl[np][sub + 2]);
                }
            #pragma unroll
            for (int mi = 0; mi < 4; mi++)
                #pragma unroll
                for (int nj = 0; nj < 4; nj++) {
                    const int np = nj >> 1, sub = nj & 1;
                    mma_bf16(acc[mi][nj], al[mi], wh[np][sub], wh[np][sub + 2]);
                }
        }
        // no trailing sync: next iteration's wait+sync separates compute(s)
        // from the buffer-reusing issue(s+2).
    }

    const int gr = lane >> 2;
    const int cp = (lane & 3) * 2;
    #pragma unroll
    for (int mi = 0; mi < 4; mi++) {
        #pragma unroll
        for (int nj = 0; nj < 4; nj++) {
            int row0 = bm + wm + mi * 16 + gr;
            int colg = colb + wn + nj * 8 + cp;
            int bcol = bn + wn + nj * 8 + cp;
            float b0 = bias[bcol], b1 = bias[bcol + 1];
            float v00 = alpha * (acc[mi][nj][0] + b0);
            float v01 = alpha * (acc[mi][nj][1] + b1);
            float v10 = alpha * (acc[mi][nj][2] + b0);
            float v11 = alpha * (acc[mi][nj][3] + b1);
            if (Cf) {
                float2 f0 = { v00, v01 }, f1 = { v10, v11 };
                *(float2*)&Cf[(size_t)row0 * GK + colg] = f0;
                *(float2*)&Cf[(size_t)(row0 + 8) * GK + colg] = f1;
            } else {
                uint32_t l0, l1;
                uint32_t h0 = pack_split(v00, v01, l0);
                uint32_t h1 = pack_split(v10, v11, l1);
                *(uint32_t*)&Ho[(size_t)row0 * GK + colg] = h0;
                *(uint32_t*)&Lo[(size_t)row0 * GK + colg] = l0;
                *(uint32_t*)&Ho[(size_t)(row0 + 8) * GK + colg] = h1;
                *(uint32_t*)&Lo[(size_t)(row0 + 8) * GK + colg] = l1;
            }
        }
    }
}

// ===========================================================================
// Flash attention: R10 structure + Q fragments hoisted to registers
// (loop-invariant; removes 16 of 80 ldsm.x4 per warp per kt iteration).
// 4 warps x 32 q-rows (mi=2), k-tile 64, term-major MMA order.
// ===========================================================================
#define ASTR 144
#define AQH_O 0
#define AQL_O (128 * ASTR)
#define ASTG0 (2 * 128 * ASTR)
#define AKH_O 0
#define AKL_O (64 * ASTR)
#define AVH_O (2 * 64 * ASTR)
#define AVL_O (3 * 64 * ASTR)
#define ABI_O (4 * 64 * ASTR)
#define ASTG_SZ (ABI_O + 256)
#define ATTN_SMEM_BYTES (ASTG0 + 2 * ASTG_SZ)   // 111104

__global__ __launch_bounds__(128, 2)
void attn_bf16_kernel(const bf16* __restrict__ Qh, const bf16* __restrict__ Ql,
                      const bf16* __restrict__ Kh, const bf16* __restrict__ Kl,
                      const bf16* __restrict__ Vh, const bf16* __restrict__ Vl,
                      const float* __restrict__ biasS,
                      bf16* __restrict__ Ch, bf16* __restrict__ Cl)
{
    extern __shared__ char smc[];
    const uint32_t sb = smem_u32(smc);
    const int b  = blockIdx.z;
    const int h  = blockIdx.y;
    const int qt = blockIdx.x;
    const int tid  = threadIdx.x;
    const int lane = tid & 31;
    const int wid  = tid >> 5;        // 0..3

    const int t  = lane & 3;
    const int gr = lane >> 2;
    const int frag_r = lane & 15;
    const int frag_k = (lane >> 4) << 3;
    const int v_kr = (lane & 7) + ((lane >> 4) << 3);
    const int v_nc = (lane & 8);

    const size_t qbase = ((size_t)b * S_LEN + (size_t)qt * 128) * GK + h * HD;

    auto issue_stage = [&](int kt, int buf) {
        const uint32_t dbase = sb + (uint32_t)(ASTG0 + buf * ASTG_SZ);
        const size_t off = ((size_t)b * S_LEN + (size_t)kt * 64) * GK + h * HD;
        const bf16* bases[4] = { Kh + off, Kl + off, Vh + off, Vl + off };
        #pragma unroll
        for (int p = 0; p < 4; p++) {
            #pragma unroll
            for (int i = 0; i < 4; i++) {
                int idx = tid + i * 128;
                int row = idx >> 3, kc = idx & 7;
                cp16(dbase + (uint32_t)(p * (64 * ASTR) + row * ASTR + kc * 16),
                     bases[p] + (size_t)row * GK + kc * 8);
            }
        }
        if (tid < 16)
            cp16(dbase + (uint32_t)(ABI_O + tid * 16),
                 biasS + (size_t)b * S_LEN + kt * 64 + tid * 4);
    };

    // prologue: Q tiles + stage 0 via cp.async
    {
        #pragma unroll
        for (int i = 0; i < 8; i++) {
            int idx = tid + i * 128;
            int row = idx >> 3, kc = idx & 7;
            cp16(sb + (uint32_t)(AQH_O + row * ASTR + kc * 16),
                 Qh + qbase + (size_t)row * GK + kc * 8);
            cp16(sb + (uint32_t)(AQL_O + row * ASTR + kc * 16),
                 Ql + qbase + (size_t)row * GK + kc * 8);
        }
        issue_stage(0, 0);
        CP_COMMIT();
    }

    // wait for Q + stage 0, then hoist Q fragments into registers (loop-invariant)
    CP_WAIT0();
    __syncthreads();
    uint32_t qa[4][2][4], ql[4][2][4];
    #pragma unroll
    for (int kk = 0; kk < 4; kk++) {
        const uint32_t kbyte = (uint32_t)((kk * 16 + frag_k) * 2);
        #pragma unroll
        for (int mi = 0; mi < 2; mi++) {
            uint32_t qo = (uint32_t)((wid * 32 + mi * 16 + frag_r) * ASTR) + kbyte;
            ldsm_x4(sb + AQH_O + qo, qa[kk][mi]);
            ldsm_x4(sb + AQL_O + qo, ql[kk][mi]);
        }
    }

    float o[2][8][4] = {};
    float m[2][2] = { { -1e30f, -1e30f }, { -1e30f, -1e30f } };
    float l[2][2] = {};

    for (int kt = 0; kt < S_LEN / 64; kt++) {
        CP_WAIT0();               // no-op for kt=0 (already drained)
        __syncthreads();
        if (kt + 1 < S_LEN / 64) {
            issue_stage(kt + 1, (kt + 1) & 1);
            CP_COMMIT();
        }
        const uint32_t stg = sb + (uint32_t)(ASTG0 + (kt & 1) * ASTG_SZ);
        const float* Bs = (const float*)(smc + ASTG0 + (kt & 1) * ASTG_SZ + ABI_O);

        // ---- S = Q K^T (3-term split, term-major per np; Q from registers)
        float s[2][8][4] = {};
        #pragma unroll
        for (int kk = 0; kk < 4; kk++) {
            const uint32_t kbyte = (uint32_t)((kk * 16 + frag_k) * 2);
            #pragma unroll
            for (int np = 0; np < 4; np++) {
                uint32_t kh[4], kl[4];
                uint32_t ko = (uint32_t)((np * 16 + frag_r) * ASTR) + kbyte;
                ldsm_x4(stg + AKH_O + ko, kh);
                ldsm_x4(stg + AKL_O + ko, kl);
                #pragma unroll
                for (int sub = 0; sub < 2; sub++)
                    #pragma unroll
                    for (int mi = 0; mi < 2; mi++)
                        mma_bf16(s[mi][np * 2 + sub], qa[kk][mi], kh[sub], kh[sub + 2]);
                #pragma unroll
                for (int sub = 0; sub < 2; sub++)
                    #pragma unroll
                    for (int mi = 0; mi < 2; mi++)
                        mma_bf16(s[mi][np * 2 + sub], qa[kk][mi], kl[sub], kl[sub + 2]);
                #pragma unroll
                for (int sub = 0; sub < 2; sub++)
                    #pragma unroll
                    for (int mi = 0; mi < 2; mi++)
                        mma_bf16(s[mi][np * 2 + sub], ql[kk][mi], kh[sub], kh[sub + 2]);
            }
        }

        // ---- online softmax (exp2 domain, precomputed bias)
        float bb0[8], bb1[8];
        #pragma unroll
        for (int nj = 0; nj < 8; nj++) {
            bb0[nj] = Bs[nj * 8 + 2 * t];
            bb1[nj] = Bs[nj * 8 + 2 * t + 1];
        }
        #pragma unroll
        for (int mi = 0; mi < 2; mi++) {
            float m0n = -1e30f, m1n = -1e30f;
            #pragma unroll
            for (int nj = 0; nj < 8; nj++) {
                s[mi][nj][0] += bb0[nj]; s[mi][nj][1] += bb1[nj];
                s[mi][nj][2] += bb0[nj]; s[mi][nj][3] += bb1[nj];
                m0n = fmaxf(m0n, fmaxf(s[mi][nj][0], s[mi][nj][1]));
                m1n = fmaxf(m1n, fmaxf(s[mi][nj][2], s[mi][nj][3]));
            }
            m0n = fmaxf(m0n, __shfl_xor_sync(0xffffffffu, m0n, 1));
            m0n = fmaxf(m0n, __shfl_xor_sync(0xffffffffu, m0n, 2));
            m1n = fmaxf(m1n, __shfl_xor_sync(0xffffffffu, m1n, 1));
            m1n = fmaxf(m1n, __shfl_xor_sync(0xffffffffu, m1n, 2));
            float m0w = fmaxf(m[mi][0], m0n);
            float m1w = fmaxf(m[mi][1], m1n);
            float a0 = ex2(m[mi][0] - m0w);
            float a1 = ex2(m[mi][1] - m1w);
            float sum0 = 0.0f, sum1 = 0.0f;
            #pragma unroll
            for (int nj = 0; nj < 8; nj++) {
                s[mi][nj][0] = ex2(s[mi][nj][0] - m0w);
                s[mi][nj][1] = ex2(s[mi][nj][1] - m0w);
                s[mi][nj][2] = ex2(s[mi][nj][2] - m1w);
                s[mi][nj][3] = ex2(s[mi][nj][3] - m1w);
                sum0 += s[mi][nj][0] + s[mi][nj][1];
                sum1 += s[mi][nj][2] + s[mi][nj][3];
            }
            l[mi][0] = l[mi][0] * a0 + sum0;
            l[mi][1] = l[mi][1] * a1 + sum1;
            m[mi][0] = m0w; m[mi][1] = m1w;
            #pragma unroll
            for (int nd = 0; nd < 8; nd++) {
                o[mi][nd][0] *= a0; o[mi][nd][1] *= a0;
                o[mi][nd][2] *= a1; o[mi][nd][3] *= a1;
            }
        }

        // ---- O += P V (3-term split, term-major per np; V via ldmatrix.trans)
        #pragma unroll
        for (int kk = 0; kk < 4; kk++) {
            const int j0 = 2 * kk, j1 = 2 * kk + 1;
            uint32_t pah[2][4], pal[2][4];
            #pragma unroll
            for (int mi = 0; mi < 2; mi++) {
                pah[mi][0] = pack_split(s[mi][j0][0], s[mi][j0][1], pal[mi][0]);
                pah[mi][1] = pack_split(s[mi][j0][2], s[mi][j0][3], pal[mi][1]);
                pah[mi][2] = pack_split(s[mi][j1][0], s[mi][j1][1], pal[mi][2]);
                pah[mi][3] = pack_split(s[mi][j1][2], s[mi][j1][3], pal[mi][3]);
            }
            #pragma unroll
            for (int np = 0; np < 4; np++) {
                uint32_t vh[4], vl[4];
                uint32_t vo = (uint32_t)((kk * 16 + v_kr) * ASTR
                                         + (np * 16 + v_nc) * 2);
                ldsm_x4_t(stg + AVH_O + vo, vh);
                ldsm_x4_t(stg + AVL_O + vo, vl);
                #pragma unroll
                for (int sub = 0; sub < 2; sub++)
                    #pragma unroll
                    for (int mi = 0; mi < 2; mi++)
                        mma_bf16(o[mi][np * 2 + sub], pah[mi], vh[sub], vh[sub + 2]);
                #pragma unroll
                for (int sub = 0; sub < 2; sub++)
                    #pragma unroll
                    for (int mi = 0; mi < 2; mi++)
                        mma_bf16(o[mi][np * 2 + sub], pah[mi], vl[sub], vl[sub + 2]);
                #pragma unroll
                for (int sub = 0; sub < 2; sub++)
                    #pragma unroll
                    for (int mi = 0; mi < 2; mi++)
                        mma_bf16(o[mi][np * 2 + sub], pal[mi], vh[sub], vh[sub + 2]);
            }
        }
        // no trailing sync (next iter's CP_WAIT0+__syncthreads suffices)
    }

    // final l reduce + write out (pre-split bf16)
    #pragma unroll
    for (int mi = 0; mi < 2; mi++) {
        float l0 = l[mi][0], l1 = l[mi][1];
        l0 += __shfl_xor_sync(0xffffffffu, l0, 1);
        l0 += __shfl_xor_sync(0xffffffffu, l0, 2);
        l1 += __shfl_xor_sync(0xffffffffu, l1, 1);
        l1 += __shfl_xor_sync(0xffffffffu, l1, 2);
        float inv0 = 1.0f / l0;
        float inv1 = 1.0f / l1;

        const size_t row0 = (size_t)b * S_LEN + (size_t)qt * 128
                          + wid * 32 + mi * 16 + gr;
        const size_t cb = row0 * GK + h * HD;
        #pragma unroll
        for (int nd = 0; nd < 8; nd++) {
            int col = nd * 8 + 2 * t;
            uint32_t lo0, lo1;
            uint32_t h0 = pack_split(o[mi][nd][0] * inv0, o[mi][nd][1] * inv0, lo0);
            uint32_t h1 = pack_split(o[mi][nd][2] * inv1, o[mi][nd][3] * inv1, lo1);
            *(uint32_t*)&Ch[cb + col] = h0;
            *(uint32_t*)&Cl[cb + col] = lo0;
            *(uint32_t*)&Ch[cb + (size_t)8 * GK + col] = h1;
            *(uint32_t*)&Cl[cb + (size_t)8 * GK + col] = lo1;
        }
    }
}

// ---------------------------------------------------------------------------
extern "C" void kernel_launch(void* const* d_in, const int* in_sizes, int n_in,
                              void* d_out, int out_size)
{
    const float* X    = (const float*)d_in[0];
    const float* mask = (const float*)d_in[1];
    const float* Wq   = (const float*)d_in[2];
    const float* bq   = (const float*)d_in[3];
    const float* Wk   = (const float*)d_in[4];
    const float* bk   = (const float*)d_in[5];
    const float* Wv   = (const float*)d_in[6];
    const float* bv   = (const float*)d_in[7];
    const float* Wo   = (const float*)d_in[8];
    const float* bo   = (const float*)d_in[9];
    float* out = (float*)d_out;

    bf16 *xh, *xl, *wh, *wl, *qh, *ql, *kh, *kl, *vh, *vl, *ch, *cl;
    float *b3, *bs;
    cudaGetSymbolAddress((void**)&xh, g_Xh);
    cudaGetSymbolAddress((void**)&xl, g_Xl);
    cudaGetSymbolAddress((void**)&wh, g_Wh);
    cudaGetSymbolAddress((void**)&wl, g_Wl);
    cudaGetSymbolAddress((void**)&qh, g_Qh);
    cudaGetSymbolAddress((void**)&ql, g_Ql);
    cudaGetSymbolAddress((void**)&kh, g_Kh);
    cudaGetSymbolAddress((void**)&kl, g_Kl);
    cudaGetSymbolAddress((void**)&vh, g_Vh);
    cudaGetSymbolAddress((void**)&vl, g_Vl);
    cudaGetSymbolAddress((void**)&ch, g_Ch);
    cudaGetSymbolAddress((void**)&cl, g_Cl);
    cudaGetSymbolAddress((void**)&b3, g_bias3);
    cudaGetSymbolAddress((void**)&bs, g_biasS);

    cudaFuncSetAttribute(gemm_bf16_kernel,
                         cudaFuncAttributeMaxDynamicSharedMemorySize,
                         GEMM_SMEM_BYTES);
    cudaFuncSetAttribute(attn_bf16_kernel,
                         cudaFuncAttributeMaxDynamicSharedMemorySize,
                         ATTN_SMEM_BYTES);

    // prep: X split, weights split (one launch), bias+mask prep (one launch)
    split_kernel<<<(M_TOTAL * GK / 4 + 255) / 256, 256>>>(X, xh, xl, M_TOTAL * GK / 4);
    split4w_kernel<<<(4 * GK * GK / 4 + 255) / 256, 256>>>(Wq, Wk, Wv, Wo, wh, wl);
    prep_misc_kernel<<<(B_SZ * S_LEN + 255) / 256, 256>>>(bq, bk, bv, mask, b3, bs);

    // fused QKV projection: N = 2304
    dim3 fgrid(3 * GK / 128, M_TOTAL / 128);   // (18, 64)
    gemm_bf16_kernel<<<fgrid, 256, GEMM_SMEM_BYTES>>>(
        xh, xl, wh, wl, b3, qh, ql, kh, kl, vh, vl, nullptr);

    dim3 agrid(S_LEN / 128, NH, B_SZ);         // (16, 12, 4)
    attn_bf16_kernel<<<agrid, 128, ATTN_SMEM_BYTES>>>(
        qh, ql, kh, kl, vh, vl, bs, ch, cl);

    // output projection (fp32 out)
    dim3 ogrid(GK / 128, M_TOTAL / 128);       // (6, 64)
    gemm_bf16_kernel<<<ogrid, 256, GEMM_SMEM_BYTES>>>(
        ch, cl, wh + 3 * GK * GK, wl + 3 * GK * GK, bo,
        nullptr, nullptr, nullptr, nullptr, nullptr, nullptr, out);
}